// round 4
// baseline (speedup 1.0000x reference)
#include <cuda_runtime.h>

// HiPoNet collapse: P = 0.5*(Wm/colsum) + 0.5*I is column-stochastic, so
// 1^T P^t = 1^T and mean_n(P^t X) = mean_n(X) exactly. Output:
//   out[b, w*160 + k*32 + d] = mean_n(pc[b,n,d]) * alphas[w,d], k=0..4.
//
// R4: same single-launch two-phase reduction as R3, but __threadfence()
// (gpu-scope => CCTL.IVALL L1-flush on sm_103a) executes in exactly ONE
// thread per block instead of all 512, twice. Ordering stays valid:
// other threads' STGs happen-before t0's fence via bar.sync, and the
// last block's readers pick up visibility via t0's acquire fence + bar.

#define NPTS    2048
#define DIM     32
#define NW      4
#define NCOLL   5
#define FOUT    (NW * NCOLL * DIM)       // 640 per batch
#define CPB     4                        // chunks per batch
#define GRID    (4 * CPB)                // 16 blocks
#define ROWS    (NPTS / CPB)             // 512 rows per chunk
#define QPR     (DIM / 4)                // 8 float4 per row
#define BLK     512
#define RG      (BLK / QPR)              // 64 row groups
#define LPT     (ROWS / RG)              // 8 loads per thread

__device__ float        g_part[4][CPB][DIM];
__device__ unsigned int g_done;          // zero-init; self-resetting

__device__ __forceinline__ float4 f4add(float4 a, float4 b) {
    return make_float4(a.x + b.x, a.y + b.y, a.z + b.z, a.w + b.w);
}

__global__ __launch_bounds__(BLK, 1)
void hiponet_kernel(const float* __restrict__ pc,
                    const float* __restrict__ alphas,
                    float* __restrict__ out)
{
    const int b  = blockIdx.x >> 2;      // batch 0..3
    const int c  = blockIdx.x & 3;       // chunk 0..3
    const int t  = threadIdx.x;          // 0..511
    const int q  = t & (QPR - 1);        // float4 slot, 0..7
    const int rg = t >> 3;               // row group, 0..63

    // Prefetch alphas early (overlaps with phase-1 DRAM latency; only the
    // last block consumes it, but the load is off the critical path here).
    __shared__ float al[NW * DIM];
    if (t < NW * DIM) al[t] = alphas[t];

    const float4* __restrict__ base =
        (const float4*)(pc + ((size_t)b * NPTS + (size_t)c * ROWS) * DIM);

    // ---- phase 1: 8 independent LDG.128, pairwise-summed for ILP ----
    float4 v[LPT];
    #pragma unroll
    for (int k = 0; k < LPT; ++k)
        v[k] = base[(size_t)(rg + k * RG) * QPR + q];
    float4 s = f4add(f4add(f4add(v[0], v[1]), f4add(v[2], v[3])),
                     f4add(f4add(v[4], v[5]), f4add(v[6], v[7])));

    __shared__ float4 sm[RG][QPR];
    sm[rg][q] = s;
    __syncthreads();

    #pragma unroll
    for (int st = RG / 2; st > 0; st >>= 1) {
        if (rg < st) sm[rg][q] = f4add(sm[rg][q], sm[rg + st][q]);
        __syncthreads();
    }

    if (t < QPR)
        ((float4*)g_part[b][c])[t] = sm[0][t];
    __syncthreads();                     // STGs happen-before t0's fence

    // ---- arrival count: single fence + atomic per block ----
    __shared__ bool is_last;
    if (t == 0) {
        __threadfence();                 // release (one CCTL.IVALL, not 512)
        unsigned v2 = atomicAdd(&g_done, 1u);
        is_last = (v2 == GRID - 1);
    }
    __syncthreads();
    if (!is_last) return;

    if (t == 0) {
        __threadfence();                 // acquire other blocks' partials
        g_done = 0;                      // reset for graph replay
    }
    __syncthreads();

    // ---- phase 2: reduce 4 partials per (b,d), write 2560 outputs ----
    __shared__ float tot[4][DIM];
    if (t < 128) {                       // bb = t>>5, d = t&31
        const int bb = t >> 5;
        const int d  = t & 31;
        float acc = (g_part[bb][0][d] + g_part[bb][1][d])
                  + (g_part[bb][2][d] + g_part[bb][3][d]);
        tot[bb][d] = acc * (1.0f / (float)NPTS);
    }
    __syncthreads();

    // 2560 outputs, 512 threads -> 5 each
    #pragma unroll
    for (int i = t; i < 4 * FOUT; i += BLK) {
        const int bb  = i / FOUT;
        const int rem = i - bb * FOUT;
        const int w   = rem / (NCOLL * DIM);
        const int d   = rem & 31;
        out[i] = tot[bb][d] * al[w * DIM + d];
    }
}

extern "C" void kernel_launch(void* const* d_in, const int* in_sizes, int n_in,
                              void* d_out, int out_size)
{
    const float* pc     = (const float*)d_in[0];  // [4, 2048, 32] fp32
    // d_in[1] = sigma: output is invariant to the diffusion operator
    const float* alphas = (const float*)d_in[2];  // [4, 32] fp32
    float* out = (float*)d_out;                   // [4, 640] fp32

    hiponet_kernel<<<GRID, BLK>>>(pc, alphas, out);
}

// round 5
// speedup vs baseline: 1.2593x; 1.2593x over previous
#include <cuda_runtime.h>

// HiPoNet collapse: P = 0.5*(Wm/colsum) + 0.5*I is column-stochastic, so
// 1^T P^t = 1^T and mean_n(P^t X) = mean_n(X) exactly. Output:
//   out[b, w*160 + k*32 + d] = mean_n(pc[b,n,d]) * alphas[w,d], k=0..4.
//
// R5: zero inter-block communication. Grid=16 = (batch b, dim-quarter dq).
// Each block reads the 32B sector (8 dims) of all 2048 rows of its batch
// (sector-granular DRAM: total traffic still 1MB, disjoint across blocks),
// reduces locally (regs -> warp bfly -> tiny shared pass), and writes its
// own disjoint 160 outputs. No atomics, no fences, no global scratch.

#define NPTS   2048
#define DIM    32
#define NW     4
#define NCOLL  5
#define FOUT   (NW * NCOLL * DIM)        // 640 per batch
#define BLK    512
#define DQ     8                         // dims per block
#define RL     (BLK / DQ)                // 64 row lanes
#define LPT    (NPTS / RL)               // 32 rows per thread

__global__ __launch_bounds__(BLK, 1)
void hiponet_kernel(const float* __restrict__ pc,
                    const float* __restrict__ alphas,
                    float* __restrict__ out)
{
    const int b  = blockIdx.x >> 2;      // batch 0..3
    const int dq = blockIdx.x & 3;       // dim quarter 0..3
    const int t  = threadIdx.x;          // 0..511
    const int dl = t & (DQ - 1);         // local dim 0..7
    const int rl = t >> 3;               // row lane 0..63

    // pointer to this block's dim sector; thread strides rows by RL
    const float* __restrict__ base =
        pc + ((size_t)b * NPTS + rl) * DIM + dq * DQ + dl;

    // ---- 32 independent scalar loads, 4 interleaved accumulators ----
    float a0 = 0.f, a1 = 0.f, a2 = 0.f, a3 = 0.f;
    #pragma unroll
    for (int k = 0; k < LPT; k += 4) {
        a0 += base[(size_t)(k + 0) * RL * DIM];
        a1 += base[(size_t)(k + 1) * RL * DIM];
        a2 += base[(size_t)(k + 2) * RL * DIM];
        a3 += base[(size_t)(k + 3) * RL * DIM];
    }
    float s = (a0 + a1) + (a2 + a3);     // sum over this thread's 32 rows

    // ---- warp reduce: lane = (rl&3)*8 + dl; combine rl's with same dl ----
    s += __shfl_xor_sync(0xffffffffu, s, 8);
    s += __shfl_xor_sync(0xffffffffu, s, 16);
    // lanes 0..7 of each warp: sum over 4 row-lanes x 32 rows = 128 rows

    __shared__ float sm[16][DQ];         // per-warp partials
    const int w = t >> 5;
    if ((t & 31) < DQ) sm[w][t & 7] = s;
    __syncthreads();

    __shared__ float mean_s[DQ];
    if (t < DQ) {                        // d = t: sum 16 warp partials
        float acc = 0.f;
        #pragma unroll
        for (int i = 0; i < 16; ++i) acc += sm[i][t];
        mean_s[t] = acc * (1.0f / (float)NPTS);
    }
    __shared__ float al[NW * DQ];        // alphas for this dim quarter
    if (t >= 32 && t < 32 + NW * DQ) {
        const int i  = t - 32;           // i = w*8 + dl
        al[i] = alphas[(i >> 3) * DIM + dq * DQ + (i & 7)];
    }
    __syncthreads();

    // ---- write this block's disjoint 160 outputs ----
    if (t < NW * NCOLL * DQ) {           // 160
        const int ww  = t / (NCOLL * DQ);          // 0..3
        const int rem = t - ww * (NCOLL * DQ);
        const int kk  = rem >> 3;                  // 0..4
        const int d2  = rem & 7;
        out[b * FOUT + ww * (NCOLL * DIM) + kk * DIM + dq * DQ + d2] =
            mean_s[d2] * al[ww * DQ + d2];
    }
}

extern "C" void kernel_launch(void* const* d_in, const int* in_sizes, int n_in,
                              void* d_out, int out_size)
{
    const float* pc     = (const float*)d_in[0];  // [4, 2048, 32] fp32
    // d_in[1] = sigma: output is invariant to the diffusion operator
    const float* alphas = (const float*)d_in[2];  // [4, 32] fp32
    float* out = (float*)d_out;                   // [4, 640] fp32

    hiponet_kernel<<<16, BLK>>>(pc, alphas, out);
}

// round 6
// speedup vs baseline: 1.3077x; 1.0385x over previous
#include <cuda_runtime.h>
#include <cstdint>

// HiPoNet collapse: P = 0.5*(Wm/colsum) + 0.5*I is column-stochastic, so
// 1^T P^t = 1^T and mean_n(P^t X) = mean_n(X) exactly. Output:
//   out[b, w*160 + k*32 + d] = mean_n(pc[b,n,d]) * alphas[w,d], k=0..4.
//
// R6: cluster(4) per batch. Each CTA reads 512 FULL 128B rows (LDG.128,
// 512 L1tex wavefronts vs 2048 for the dim-partitioned R5), reduces to a
// 32-dim partial in shared, cluster-barriers, pulls peers' partials over
// DSMEM (one parallel 215-cyc round), and writes its disjoint dim-quarter
// (160 floats) of the output. No atomics, no gpu-scope fences.

#define NPTS   2048
#define DIM    32
#define NW     4
#define NCOLL  5
#define FOUT   (NW * NCOLL * DIM)        // 640 per batch
#define CSZ    4                         // cluster size = CTAs per batch
#define BLK    512
#define ROWS   (NPTS / CSZ)              // 512 rows per CTA
#define QPR    (DIM / 4)                 // 8 float4 per row
#define RG     (BLK / QPR)               // 64 row groups
#define LPT    (ROWS / RG)               // 8 loads per thread
#define DQ     (DIM / CSZ)               // 8 dims owned per CTA

__device__ __forceinline__ float4 f4add(float4 a, float4 b) {
    return make_float4(a.x + b.x, a.y + b.y, a.z + b.z, a.w + b.w);
}

__device__ __forceinline__ uint32_t smem_u32(const void* p) {
    uint32_t a;
    asm("{ .reg .u64 t; cvta.to.shared.u64 t, %1; cvt.u32.u64 %0, t; }"
        : "=r"(a) : "l"(p));
    return a;
}

__device__ __forceinline__ float dsmem_read_f32(uint32_t laddr, uint32_t rank) {
    uint32_t raddr; float v;
    asm("mapa.shared::cluster.u32 %0, %1, %2;" : "=r"(raddr) : "r"(laddr), "r"(rank));
    asm volatile("ld.shared::cluster.f32 %0, [%1];" : "=f"(v) : "r"(raddr));
    return v;
}

__global__ __launch_bounds__(BLK, 1) __cluster_dims__(CSZ, 1, 1)
void hiponet_kernel(const float* __restrict__ pc,
                    const float* __restrict__ alphas,
                    float* __restrict__ out)
{
    const int b = blockIdx.x >> 2;       // batch 0..3 (cluster id)
    uint32_t rank;
    asm("mov.u32 %0, %%cluster_ctarank;" : "=r"(rank));  // 0..3
    const int t  = threadIdx.x;          // 0..511
    const int q  = t & (QPR - 1);        // float4 slot, 0..7
    const int rg = t >> 3;               // row group, 0..63

    __shared__ float4 sm[RG][QPR];
    __shared__ float  partial[DIM];      // this CTA's 32-dim partial sum
    __shared__ float  tots[CSZ][DQ];     // peers' partials for my dim quarter
    __shared__ float  mean_s[DQ];
    __shared__ float  al[NW * DQ];       // alphas for my dim quarter

    // alphas prefetch (dims rank*8 .. rank*8+7), overlaps DRAM latency
    if (t < NW * DQ)
        al[t] = alphas[(t >> 3) * DIM + rank * DQ + (t & 7)];

    // ---- full-line loads: 512 rows x 128B, 8 independent LDG.128/thread ----
    const float4* __restrict__ base =
        (const float4*)(pc + ((size_t)b * NPTS + rank * ROWS) * DIM);

    float4 v[LPT];
    #pragma unroll
    for (int k = 0; k < LPT; ++k)
        v[k] = base[(size_t)(rg + k * RG) * QPR + q];
    float4 s = f4add(f4add(f4add(v[0], v[1]), f4add(v[2], v[3])),
                     f4add(f4add(v[4], v[5]), f4add(v[6], v[7])));

    sm[rg][q] = s;
    __syncthreads();

    #pragma unroll
    for (int st = RG / 2; st > 0; st >>= 1) {
        if (rg < st) sm[rg][q] = f4add(sm[rg][q], sm[rg + st][q]);
        __syncthreads();
    }
    if (t < QPR) ((float4*)partial)[t] = sm[0][t];
    __syncthreads();

    // ---- cluster barrier #1: partials visible cluster-wide ----
    asm volatile("barrier.cluster.arrive.aligned;" ::: "memory");
    asm volatile("barrier.cluster.wait.aligned;"   ::: "memory");

    // ---- pull the 4 partials for my dim quarter (parallel DSMEM reads) ----
    const uint32_t part_addr = smem_u32(partial);
    if (t < CSZ * DQ) {                  // 32 threads: c = t>>3, dl = t&7
        const uint32_t c  = t >> 3;
        const int      dl = t & 7;
        tots[c][dl] = dsmem_read_f32(
            part_addr + (uint32_t)(rank * DQ + dl) * 4u, c);
    }
    __syncthreads();

    if (t < DQ) {
        mean_s[t] = ((tots[0][t] + tots[1][t]) + (tots[2][t] + tots[3][t]))
                    * (1.0f / (float)NPTS);
    }
    __syncthreads();

    // ---- write my disjoint 160 outputs ----
    if (t < NW * NCOLL * DQ) {           // 160
        const int ww  = t / (NCOLL * DQ);
        const int rem = t - ww * (NCOLL * DQ);
        const int kk  = rem >> 3;
        const int dl  = rem & 7;
        out[b * FOUT + ww * (NCOLL * DIM) + kk * DIM + rank * DQ + dl] =
            mean_s[dl] * al[ww * DQ + dl];
    }

    // ---- cluster barrier #2: keep SMEM alive until all peers read it ----
    asm volatile("barrier.cluster.arrive.aligned;" ::: "memory");
    asm volatile("barrier.cluster.wait.aligned;"   ::: "memory");
}

extern "C" void kernel_launch(void* const* d_in, const int* in_sizes, int n_in,
                              void* d_out, int out_size)
{
    const float* pc     = (const float*)d_in[0];  // [4, 2048, 32] fp32
    // d_in[1] = sigma: output is invariant to the diffusion operator
    const float* alphas = (const float*)d_in[2];  // [4, 32] fp32
    float* out = (float*)d_out;                   // [4, 640] fp32

    hiponet_kernel<<<16, BLK>>>(pc, alphas, out);
}

// round 7
// speedup vs baseline: 1.3140x; 1.0048x over previous
#include <cuda_runtime.h>

// HiPoNet collapse: P = 0.5*(Wm/colsum) + 0.5*I is column-stochastic, so
// 1^T P^t = 1^T and mean_n(P^t X) = mean_n(X) exactly. Output:
//   out[b, w*160 + k*32 + d] = mean_n(pc[b,n,d]) * alphas[w,d], k=0..4.
//
// R7: zero-communication sector partition (best measured structure, R5)
// with vectorized sector loads. Grid=16 = (batch b, dim-quarter dq).
// Each block reads the 32B sector of all 2048 rows as float4 (2 thr/row,
// 8 independent LDG.128/thread -> 128 warp-LDGs/SM vs 512 scalar), then
// float4 butterfly-shuffle reduce + one tiny shared pass. No atomics,
// no fences, no clusters.

#define NPTS   2048
#define DIM    32
#define NW     4
#define NCOLL  5
#define FOUT   (NW * NCOLL * DIM)        // 640 per batch
#define BLK    512
#define DQ     8                         // dims per block (one 32B sector)
#define RPP    (BLK / 2)                 // 256 rows per pass
#define LPT    (NPTS / RPP)              // 8 loads per thread

__device__ __forceinline__ float4 f4add(float4 a, float4 b) {
    return make_float4(a.x + b.x, a.y + b.y, a.z + b.z, a.w + b.w);
}

__device__ __forceinline__ float4 f4shfl_xor(float4 v, int m) {
    v.x += __shfl_xor_sync(0xffffffffu, v.x, m);
    v.y += __shfl_xor_sync(0xffffffffu, v.y, m);
    v.z += __shfl_xor_sync(0xffffffffu, v.z, m);
    v.w += __shfl_xor_sync(0xffffffffu, v.w, m);
    return v;
}

__global__ __launch_bounds__(BLK, 1)
void hiponet_kernel(const float* __restrict__ pc,
                    const float* __restrict__ alphas,
                    float* __restrict__ out)
{
    const int b    = blockIdx.x >> 2;    // batch 0..3
    const int dq   = blockIdx.x & 3;     // dim quarter 0..3
    const int t    = threadIdx.x;        // 0..511
    const int half = t & 1;              // which float4 of the 32B sector
    const int r    = t >> 1;             // row lane 0..255

    __shared__ float sm[16][DQ];         // per-warp partials (dims of block)
    __shared__ float mean_s[DQ];
    __shared__ float al[NW * DQ];

    // alphas prefetch for this dim quarter (overlaps DRAM latency)
    if (t < NW * DQ)
        al[t] = alphas[(t >> 3) * DIM + dq * DQ + (t & 7)];

    // ---- 8 independent LDG.128 per thread over the block's sector ----
    const float4* __restrict__ base =
        (const float4*)pc + ((size_t)b * NPTS + r) * (DIM / 4) + dq * 2 + half;

    float4 v[LPT];
    #pragma unroll
    for (int k = 0; k < LPT; ++k)
        v[k] = base[(size_t)k * RPP * (DIM / 4)];
    float4 s = f4add(f4add(f4add(v[0], v[1]), f4add(v[2], v[3])),
                     f4add(f4add(v[4], v[5]), f4add(v[6], v[7])));

    // ---- butterfly over row lanes (parity bit 0 = half stays fixed) ----
    s = f4shfl_xor(s, 2);
    s = f4shfl_xor(s, 4);
    s = f4shfl_xor(s, 8);
    s = f4shfl_xor(s, 16);
    // lanes 0 (half 0) and 1 (half 1) hold this warp's 128-row sums

    if ((t & 31) < 2)
        *(float4*)&sm[t >> 5][half * 4] = s;
    __syncthreads();

    if (t < DQ) {                        // dl = t: sum 16 warp partials
        float acc = 0.f;
        #pragma unroll
        for (int i = 0; i < 16; ++i) acc += sm[i][t];
        mean_s[t] = acc * (1.0f / (float)NPTS);
    }
    __syncthreads();

    // ---- write this block's disjoint 160 outputs ----
    if (t < NW * NCOLL * DQ) {           // 160
        const int ww  = t / (NCOLL * DQ);
        const int rem = t - ww * (NCOLL * DQ);
        const int kk  = rem >> 3;
        const int dl  = rem & 7;
        out[b * FOUT + ww * (NCOLL * DIM) + kk * DIM + dq * DQ + dl] =
            mean_s[dl] * al[ww * DQ + dl];
    }
}

extern "C" void kernel_launch(void* const* d_in, const int* in_sizes, int n_in,
                              void* d_out, int out_size)
{
    const float* pc     = (const float*)d_in[0];  // [4, 2048, 32] fp32
    // d_in[1] = sigma: output is invariant to the diffusion operator
    const float* alphas = (const float*)d_in[2];  // [4, 32] fp32
    float* out = (float*)d_out;                   // [4, 640] fp32

    hiponet_kernel<<<16, BLK>>>(pc, alphas, out);
}